// round 15
// baseline (speedup 1.0000x reference)
#include <cuda_runtime.h>
#include <cuda_fp16.h>
#include <cstdint>

#define N_NODES 100000
#define N_EDGES 800000
#define C 64

#define SCAN_CHUNK 1024
#define NB_SCAN ((N_NODES + SCAN_CHUNK - 1) / SCAN_CHUNK)  // 98
#define G1_ROWS 128
#define G1_TILES ((N_NODES + G1_ROWS - 1) / G1_ROWS)       // 782
#define COUNT_BLOCKS ((N_EDGES / 4 + 255) / 256)           // 782
#define GL_ROWS 64
#define GL_TILES ((N_NODES + GL_ROWS - 1) / GL_ROWS)       // 1563
#define G2_ROWS 64
#define G2_TILES ((N_NODES + G2_ROWS - 1) / G2_ROWS)       // 1563
#define FILL_BLOCKS ((N_EDGES + 255) / 256)                // 3125
#define SCALE_ROWS 128
#define SCALE_BLOCKS ((N_NODES + SCALE_ROWS - 1) / SCALE_ROWS)  // 782

// Scratch (device globals — zero-initialized at module load; g_cnt's
// "zero on entry" invariant is restored by k_gemm2 every run)
__device__ __half2 g_hh[(size_t)N_NODES * 32]; // x@W; after k_fill: scaled by dinv[row]
__device__ __half2 g_rs[(size_t)N_NODES * 32]; // gated LN output, fp16x2 (12.8MB)
__device__ int     g_cnt[N_NODES];             // in-degree (excl. self-loop)
__device__ float   g_dinv[N_NODES];            // rsqrt(1 + cnt)
__device__ int2    g_offcnt[N_NODES];          // {CSR start, degree} fused
__device__ int     g_cursor[N_NODES];          // bucket-fill cursors
__device__ int     g_srcs[N_EDGES];            // CSR column (src) indices

// ---- Blackwell packed f32x2 helpers (FFMA2: 2 fp32 FMAs per issue) --------
__device__ __forceinline__ unsigned long long pack2(float lo, float hi) {
    unsigned long long r;
    asm("mov.b64 %0, {%1, %2};" : "=l"(r) : "f"(lo), "f"(hi));
    return r;
}
__device__ __forceinline__ void unpack2(unsigned long long v, float& lo, float& hi) {
    asm("mov.b64 {%0, %1}, %2;" : "=f"(lo), "=f"(hi) : "l"(v));
}
__device__ __forceinline__ unsigned long long ffma2(unsigned long long a,
                                                    unsigned long long b,
                                                    unsigned long long c) {
    unsigned long long d;
    asm("fma.rn.f32x2 %0, %1, %2, %3;" : "=l"(d) : "l"(a), "l"(b), "l"(c));
    return d;
}

// ---------------------------------------------------------------------------
// K1: merged GEMM1 + degree count.
// ---------------------------------------------------------------------------
__global__ __launch_bounds__(256) void k_count_gemm(const float* __restrict__ x,
                                                    const float* __restrict__ W,
                                                    const int* __restrict__ ei) {
    __shared__ float Ws[64 * 64];      // k-major
    __shared__ float xs[G1_ROWS][68];

    int tid = threadIdx.x;

    if (blockIdx.x >= G1_TILES) {
        int idx = (blockIdx.x - G1_TILES) * 256 + tid;
        int e4 = idx * 4;
        if (e4 + 3 < N_EDGES) {
            int4 d = *(const int4*)&ei[N_EDGES + e4];
            atomicAdd(&g_cnt[d.x], 1);
            atomicAdd(&g_cnt[d.y], 1);
            atomicAdd(&g_cnt[d.z], 1);
            atomicAdd(&g_cnt[d.w], 1);
        } else {
            for (int j = 0; j < 4; j++)
                if (e4 + j < N_EDGES) atomicAdd(&g_cnt[ei[N_EDGES + e4 + j]], 1);
        }
        return;
    }

    long long rowbase = (long long)blockIdx.x * G1_ROWS;

#pragma unroll
    for (int i = 0; i < 4; i++)
        ((float4*)Ws)[tid + 256 * i] = ((const float4*)W)[tid + 256 * i];

#pragma unroll
    for (int i = 0; i < 8; i++) {
        int f = tid + i * 256;
        int r = f >> 4, kq = f & 15;
        long long grow = rowbase + r;
        float4 v = make_float4(0.f, 0.f, 0.f, 0.f);
        if (grow < N_NODES) v = *(const float4*)&x[grow * 64 + kq * 4];
        *(float4*)&xs[r][kq * 4] = v;
    }
    __syncthreads();

    int tx = tid & 15;
    int ty = tid >> 4;
    int r0 = ty * 8;
    int c0 = tx * 4;

    unsigned long long a01[8], a23[8];
#pragma unroll
    for (int i = 0; i < 8; i++) { a01[i] = 0ull; a23[i] = 0ull; }

#pragma unroll
    for (int k0 = 0; k0 < 64; k0 += 4) {
        float4 xv[8];
#pragma unroll
        for (int i = 0; i < 8; i++) xv[i] = *(float4*)&xs[r0 + i][k0];
#pragma unroll
        for (int kk = 0; kk < 4; kk++) {
            float4 w = *(float4*)&Ws[(k0 + kk) * 64 + c0];
            unsigned long long w01 = pack2(w.x, w.y);
            unsigned long long w23 = pack2(w.z, w.w);
#pragma unroll
            for (int i = 0; i < 8; i++) {
                float xk = (kk == 0) ? xv[i].x : (kk == 1) ? xv[i].y
                         : (kk == 2) ? xv[i].z : xv[i].w;
                unsigned long long xx = pack2(xk, xk);
                a01[i] = ffma2(xx, w01, a01[i]);
                a23[i] = ffma2(xx, w23, a23[i]);
            }
        }
    }

#pragma unroll
    for (int i = 0; i < 8; i++) {
        long long row = rowbase + r0 + i;
        if (row < N_NODES) {
            float b0, b1, b2, b3;
            unpack2(a01[i], b0, b1);
            unpack2(a23[i], b2, b3);
            __half2* dst = &g_hh[row * 32 + (c0 >> 1)];
            dst[0] = __floats2half2_rn(b0, b1);
            dst[1] = __floats2half2_rn(b2, b3);
        }
    }
}

// ---------------------------------------------------------------------------
// K2: single-kernel scan -> offcnt (fused), cursors, dinv.
// ---------------------------------------------------------------------------
__global__ __launch_bounds__(256) void k_scan() {
    __shared__ int wsum[8], woff[8];
    __shared__ int sBase;
    int tid = threadIdx.x;
    int lane = tid & 31, wid = tid >> 5;

    int nPre = blockIdx.x * SCAN_CHUNK;
    int pre = 0;
#pragma unroll 4
    for (int i = tid * 4; i < nPre; i += 256 * 4) {
        int4 v = *(const int4*)&g_cnt[i];
        pre += v.x + v.y + v.z + v.w;
    }
#pragma unroll
    for (int o = 16; o; o >>= 1) pre += __shfl_down_sync(0xFFFFFFFFu, pre, o);
    if (lane == 0) wsum[wid] = pre;
    __syncthreads();
    if (tid == 0) {
        int t = 0;
#pragma unroll
        for (int i = 0; i < 8; i++) t += wsum[i];
        sBase = t;
    }
    __syncthreads();

    int base = blockIdx.x * SCAN_CHUNK + tid * 4;
    int v[4];
    if (base + 3 < N_NODES) {
        int4 t = *(const int4*)&g_cnt[base];
        v[0] = t.x; v[1] = t.y; v[2] = t.z; v[3] = t.w;
    } else {
#pragma unroll
        for (int j = 0; j < 4; j++)
            v[j] = (base + j < N_NODES) ? g_cnt[base + j] : 0;
    }
    int tsum = v[0] + v[1] + v[2] + v[3];

    int inc = tsum;
#pragma unroll
    for (int o = 1; o < 32; o <<= 1) {
        int y = __shfl_up_sync(0xFFFFFFFFu, inc, o);
        if (lane >= o) inc += y;
    }
    if (lane == 31) wsum[wid] = inc;
    __syncthreads();
    if (wid == 0) {
        int s = (lane < 8) ? wsum[lane] : 0;
        int orig = s;
#pragma unroll
        for (int o = 1; o < 8; o <<= 1) {
            int y = __shfl_up_sync(0xFFFFFFFFu, s, o);
            if (lane >= o) s += y;
        }
        if (lane < 8) woff[lane] = s - orig;
    }
    __syncthreads();

    int off = sBase + woff[wid] + (inc - tsum);
#pragma unroll
    for (int j = 0; j < 4; j++) {
        int i = base + j;
        if (i < N_NODES) {
            g_offcnt[i] = make_int2(off, v[j]);
            g_cursor[i] = off;
            g_dinv[i] = rsqrtf(1.0f + (float)v[j]);
        }
        off += v[j];
    }
}

// ---------------------------------------------------------------------------
// K3: hh pre-scale (blocks 0..SCALE_BLOCKS, FIRST so it overlaps fill)
//     + bucket fill (remaining blocks, 1 edge/thread).
// ---------------------------------------------------------------------------
__global__ __launch_bounds__(256) void k_fill(const int* __restrict__ ei) {
    if (blockIdx.x < SCALE_BLOCKS) {
        int w = threadIdx.x >> 5;
        int l = threadIdx.x & 31;
        int rowbase = blockIdx.x * SCALE_ROWS + w * 16;
#pragma unroll
        for (int i = 0; i < 16; i++) {
            int row = rowbase + i;
            if (row < N_NODES) {
                float d = g_dinv[row];
                unsigned idx = (unsigned)row * 32u + l;
                float2 v = __half22float2(g_hh[idx]);
                g_hh[idx] = __floats2half2_rn(v.x * d, v.y * d);
            }
        }
        return;
    }
    int e = (blockIdx.x - SCALE_BLOCKS) * 256 + threadIdx.x;
    if (e < N_EDGES) {
        int src = ei[e];
        int dst = ei[N_EDGES + e];
        g_srcs[atomicAdd(&g_cursor[dst], 1)] = src;
    }
}

// ---------------------------------------------------------------------------
// K4: gather + LN + ReLU + x-gate -> g_rs (fp16).
// 2 nodes per warp (16 lanes x 4 cols). Inner loop accumulates each
// 4-neighbor batch PAIRWISE IN FP16 (6 HADD2 + 2 cvt + 4 FADD vs 8 cvt +
// 16 FADD) — kernel was issue-bound (61.9%) at R14. Gate vector x is
// prefetched before the gather loop; off/cnt fused into one int2 load.
// ---------------------------------------------------------------------------
__global__ __launch_bounds__(256) void k_gather_ln(
        const float* __restrict__ x,
        const float* __restrict__ b,
        const float* __restrict__ gamma,
        const float* __restrict__ beta) {
    __shared__ float sb[64], sg[64], sbe[64];

    int tid = threadIdx.x;
    int rowbase = blockIdx.x * GL_ROWS;

    if (tid < 64) {
        sb[tid] = b[tid];
        sg[tid] = gamma[tid];
        sbe[tid] = beta[tid];
    }
    __syncthreads();

    int w = tid >> 5;          // warp 0..7
    int l = tid & 31;
    int h = l >> 4;            // which node of the pair (0/1)
    int c = l & 15;            // col group: cols 4c..4c+3
    int cc = 4 * c;

#pragma unroll
    for (int p = 0; p < 4; p++) {
        int node = rowbase + w * 8 + p * 2 + h;
        bool valid = node < N_NODES;

        int start = 0, deg = 0;
        float dinv = 0.f;
        float4 xv = make_float4(0.f, 0.f, 0.f, 0.f);
        if (valid) {
            int2 oc = g_offcnt[node];
            start = oc.x;
            deg = oc.y;
            dinv = g_dinv[node];
            xv = *(const float4*)&x[(unsigned)node * 64u + cc];  // prefetch gate
        }

        // self-loop term (hh already scaled by dinv[node])
        float a0 = 0.f, a1 = 0.f, a2 = 0.f, a3 = 0.f;
        if (valid) {
            uint2 u = *(const uint2*)&g_hh[(unsigned)node * 32u + 2 * c];
            float2 lo = __half22float2(*reinterpret_cast<__half2*>(&u.x));
            float2 hi = __half22float2(*reinterpret_cast<__half2*>(&u.y));
            a0 = lo.x; a1 = lo.y; a2 = hi.x; a3 = hi.y;
        }

        // warp-uniform trip count; per-slot predication
        int degMax = max(deg, __shfl_xor_sync(0xFFFFFFFFu, deg, 16));
        for (int it = 0; it < degMax; it += 4) {
            unsigned s[4];
            bool pq[4];
#pragma unroll
            for (int j = 0; j < 4; j++) {
                pq[j] = (it + j) < deg;
                s[j] = pq[j] ? (unsigned)g_srcs[start + it + j] : 0u;
            }
            uint2 u[4];
#pragma unroll
            for (int j = 0; j < 4; j++)
                u[j] = pq[j] ? *(const uint2*)&g_hh[s[j] * 32u + 2 * c]
                             : make_uint2(0u, 0u);
            // pairwise fp16 tree per column pair (same columns across nbrs)
            __half2 hx = __hadd2(__hadd2(*reinterpret_cast<__half2*>(&u[0].x),
                                         *reinterpret_cast<__half2*>(&u[1].x)),
                                 __hadd2(*reinterpret_cast<__half2*>(&u[2].x),
                                         *reinterpret_cast<__half2*>(&u[3].x)));
            __half2 hy = __hadd2(__hadd2(*reinterpret_cast<__half2*>(&u[0].y),
                                         *reinterpret_cast<__half2*>(&u[1].y)),
                                 __hadd2(*reinterpret_cast<__half2*>(&u[2].y),
                                         *reinterpret_cast<__half2*>(&u[3].y)));
            float2 fx = __half22float2(hx);
            float2 fy = __half22float2(hy);
            a0 += fx.x; a1 += fx.y; a2 += fy.x; a3 += fy.y;
        }

        float v0 = a0 * dinv + sb[cc];
        float v1 = a1 * dinv + sb[cc + 1];
        float v2 = a2 * dinv + sb[cc + 2];
        float v3 = a3 * dinv + sb[cc + 3];

        float s4 = v0 + v1 + v2 + v3;
        float q4 = v0 * v0 + v1 * v1 + v2 * v2 + v3 * v3;
#pragma unroll
        for (int o = 8; o; o >>= 1) {     // reduce over 16 lanes
            s4 += __shfl_xor_sync(0xFFFFFFFFu, s4, o);
            q4 += __shfl_xor_sync(0xFFFFFFFFu, q4, o);
        }
        float mu = s4 * (1.0f / 64.0f);
        float var = q4 * (1.0f / 64.0f) - mu * mu;
        float inv = rsqrtf(var + 1e-5f);

        if (valid) {
            float t0 = fmaxf((v0 - mu) * inv * sg[cc]     + sbe[cc],     0.f) * xv.x;
            float t1 = fmaxf((v1 - mu) * inv * sg[cc + 1] + sbe[cc + 1], 0.f) * xv.y;
            float t2 = fmaxf((v2 - mu) * inv * sg[cc + 2] + sbe[cc + 2], 0.f) * xv.z;
            float t3 = fmaxf((v3 - mu) * inv * sg[cc + 3] + sbe[cc + 3], 0.f) * xv.w;
            uint2 o2;
            __half2 h01 = __floats2half2_rn(t0, t1);
            __half2 h23 = __floats2half2_rn(t2, t3);
            o2.x = *reinterpret_cast<unsigned*>(&h01);
            o2.y = *reinterpret_cast<unsigned*>(&h23);
            *(uint2*)&g_rs[(unsigned)node * 32u + 2 * c] = o2;
        }
    }
}

// ---------------------------------------------------------------------------
// K5: GEMM2 — out = rs @ fcW + fcb. 64-row tiles; fp16->fp32 at staging;
// 4x4 f32x2 micro-tile. Also resets g_cnt for the next run.
// ---------------------------------------------------------------------------
__global__ __launch_bounds__(256) void k_gemm2(const float* __restrict__ fcW,
                                               const float* __restrict__ fcb,
                                               float* __restrict__ out) {
    __shared__ float Ws[64 * 64];
    __shared__ float xs[G2_ROWS][68];
    __shared__ float sfcb[64];

    int tid = threadIdx.x;
    int rowbase = blockIdx.x * G2_ROWS;

#pragma unroll
    for (int i = 0; i < 4; i++)
        ((float4*)Ws)[tid + 256 * i] = ((const float4*)fcW)[tid + 256 * i];
    if (tid < 64) sfcb[tid] = fcb[tid];

#pragma unroll
    for (int i = 0; i < 4; i++) {
        int f = tid + i * 256;
        int r = f >> 4, kq = f & 15;
        int row = rowbase + r;
        uint2 u = make_uint2(0u, 0u);
        if (row < N_NODES) u = *(const uint2*)&g_rs[(unsigned)row * 32u + kq * 2];
        float2 lo = __half22float2(*reinterpret_cast<__half2*>(&u.x));
        float2 hi = __half22float2(*reinterpret_cast<__half2*>(&u.y));
        *(float4*)&xs[r][kq * 4] = make_float4(lo.x, lo.y, hi.x, hi.y);
    }

    if (tid < G2_ROWS) {
        int row = rowbase + tid;
        if (row < N_NODES) g_cnt[row] = 0;
    }
    __syncthreads();

    int tx = tid & 15;
    int ty = tid >> 4;
    int r0 = ty * 4;
    int c0 = tx * 4;

    unsigned long long a01[4], a23[4];
#pragma unroll
    for (int i = 0; i < 4; i++) { a01[i] = 0ull; a23[i] = 0ull; }

#pragma unroll
    for (int k0 = 0; k0 < 64; k0 += 4) {
        float4 xv[4];
#pragma unroll
        for (int i = 0; i < 4; i++) xv[i] = *(float4*)&xs[r0 + i][k0];
#pragma unroll
        for (int kk = 0; kk < 4; kk++) {
            float4 wv = *(float4*)&Ws[(k0 + kk) * 64 + c0];
            unsigned long long w01 = pack2(wv.x, wv.y);
            unsigned long long w23 = pack2(wv.z, wv.w);
#pragma unroll
            for (int i = 0; i < 4; i++) {
                float xk = (kk == 0) ? xv[i].x : (kk == 1) ? xv[i].y
                         : (kk == 2) ? xv[i].z : xv[i].w;
                unsigned long long xx = pack2(xk, xk);
                a01[i] = ffma2(xx, w01, a01[i]);
                a23[i] = ffma2(xx, w23, a23[i]);
            }
        }
    }

#pragma unroll
    for (int i = 0; i < 4; i++) {
        int row = rowbase + r0 + i;
        if (row < N_NODES) {
            float b0, b1, b2, b3;
            unpack2(a01[i], b0, b1);
            unpack2(a23[i], b2, b3);
            *(float4*)&out[(unsigned)row * 64u + c0] =
                make_float4(b0 + sfcb[c0], b1 + sfcb[c0 + 1],
                            b2 + sfcb[c0 + 2], b3 + sfcb[c0 + 3]);
        }
    }
}

// ---------------------------------------------------------------------------
extern "C" void kernel_launch(void* const* d_in, const int* in_sizes, int n_in,
                              void* d_out, int out_size) {
    const float* x     = (const float*)d_in[0];
    const int*   ei    = (const int*)d_in[1];   // int32 per harness metadata
    const float* W     = (const float*)d_in[2];
    const float* b     = (const float*)d_in[3];
    const float* gamma = (const float*)d_in[4];
    const float* beta  = (const float*)d_in[5];
    const float* fcW   = (const float*)d_in[6];
    const float* fcb   = (const float*)d_in[7];
    float* out = (float*)d_out;

    (void)in_sizes; (void)n_in; (void)out_size;

    k_count_gemm<<<G1_TILES + COUNT_BLOCKS, 256>>>(x, W, ei);
    k_scan<<<NB_SCAN, 256>>>();
    k_fill<<<SCALE_BLOCKS + FILL_BLOCKS, 256>>>(ei);
    k_gather_ln<<<GL_TILES, 256>>>(x, b, gamma, beta);
    k_gemm2<<<G2_TILES, 256>>>(fcW, fcb, out);
}

// round 16
// speedup vs baseline: 1.0268x; 1.0268x over previous
#include <cuda_runtime.h>
#include <cuda_fp16.h>
#include <cstdint>

#define N_NODES 100000
#define N_EDGES 800000
#define C 64

#define SCAN_CHUNK 1024
#define NB_SCAN ((N_NODES + SCAN_CHUNK - 1) / SCAN_CHUNK)  // 98
#define G1_ROWS 128
#define G1_TILES ((N_NODES + G1_ROWS - 1) / G1_ROWS)       // 782
#define COUNT_BLOCKS ((N_EDGES / 4 + 255) / 256)           // 782
#define GL_ROWS 64
#define GL_TILES ((N_NODES + GL_ROWS - 1) / GL_ROWS)       // 1563
#define G2_ROWS 128
#define G2_TILES ((N_NODES + G2_ROWS - 1) / G2_ROWS)       // 782
#define FILL_BLOCKS ((N_EDGES + 255) / 256)                // 3125
#define SCALE_ROWS 128
#define SCALE_BLOCKS ((N_NODES + SCALE_ROWS - 1) / SCALE_ROWS)  // 782

// Scratch (device globals — zero-initialized at module load; g_cnt's
// "zero on entry" invariant is restored by k_gemm2 every run)
__device__ __half2 g_hh[(size_t)N_NODES * 32]; // x@W; after k_fill: scaled by dinv[row]
__device__ __half2 g_rs[(size_t)N_NODES * 32]; // gated LN output, fp16x2 (12.8MB)
__device__ int     g_cnt[N_NODES];             // in-degree (excl. self-loop)
__device__ float   g_dinv[N_NODES];            // rsqrt(1 + cnt)
__device__ int2    g_offcnt[N_NODES];          // {CSR start, degree} fused
__device__ int     g_cursor[N_NODES];          // bucket-fill cursors
__device__ int     g_srcs[N_EDGES];            // CSR column (src) indices

// ---- Blackwell packed f32x2 helpers (FFMA2: 2 fp32 FMAs per issue) --------
__device__ __forceinline__ unsigned long long pack2(float lo, float hi) {
    unsigned long long r;
    asm("mov.b64 %0, {%1, %2};" : "=l"(r) : "f"(lo), "f"(hi));
    return r;
}
__device__ __forceinline__ void unpack2(unsigned long long v, float& lo, float& hi) {
    asm("mov.b64 {%0, %1}, %2;" : "=f"(lo), "=f"(hi) : "l"(v));
}
__device__ __forceinline__ unsigned long long ffma2(unsigned long long a,
                                                    unsigned long long b,
                                                    unsigned long long c) {
    unsigned long long d;
    asm("fma.rn.f32x2 %0, %1, %2, %3;" : "=l"(d) : "l"(a), "l"(b), "l"(c));
    return d;
}

// ---------------------------------------------------------------------------
// K1: merged GEMM1 + degree count.
// ---------------------------------------------------------------------------
__global__ __launch_bounds__(256) void k_count_gemm(const float* __restrict__ x,
                                                    const float* __restrict__ W,
                                                    const int* __restrict__ ei) {
    __shared__ float Ws[64 * 64];      // k-major
    __shared__ float xs[G1_ROWS][68];

    int tid = threadIdx.x;

    if (blockIdx.x >= G1_TILES) {
        int idx = (blockIdx.x - G1_TILES) * 256 + tid;
        int e4 = idx * 4;
        if (e4 + 3 < N_EDGES) {
            int4 d = *(const int4*)&ei[N_EDGES + e4];
            atomicAdd(&g_cnt[d.x], 1);
            atomicAdd(&g_cnt[d.y], 1);
            atomicAdd(&g_cnt[d.z], 1);
            atomicAdd(&g_cnt[d.w], 1);
        } else {
            for (int j = 0; j < 4; j++)
                if (e4 + j < N_EDGES) atomicAdd(&g_cnt[ei[N_EDGES + e4 + j]], 1);
        }
        return;
    }

    long long rowbase = (long long)blockIdx.x * G1_ROWS;

#pragma unroll
    for (int i = 0; i < 4; i++)
        ((float4*)Ws)[tid + 256 * i] = ((const float4*)W)[tid + 256 * i];

#pragma unroll
    for (int i = 0; i < 8; i++) {
        int f = tid + i * 256;
        int r = f >> 4, kq = f & 15;
        long long grow = rowbase + r;
        float4 v = make_float4(0.f, 0.f, 0.f, 0.f);
        if (grow < N_NODES) v = *(const float4*)&x[grow * 64 + kq * 4];
        *(float4*)&xs[r][kq * 4] = v;
    }
    __syncthreads();

    int tx = tid & 15;
    int ty = tid >> 4;
    int r0 = ty * 8;
    int c0 = tx * 4;

    unsigned long long a01[8], a23[8];
#pragma unroll
    for (int i = 0; i < 8; i++) { a01[i] = 0ull; a23[i] = 0ull; }

#pragma unroll
    for (int k0 = 0; k0 < 64; k0 += 4) {
        float4 xv[8];
#pragma unroll
        for (int i = 0; i < 8; i++) xv[i] = *(float4*)&xs[r0 + i][k0];
#pragma unroll
        for (int kk = 0; kk < 4; kk++) {
            float4 w = *(float4*)&Ws[(k0 + kk) * 64 + c0];
            unsigned long long w01 = pack2(w.x, w.y);
            unsigned long long w23 = pack2(w.z, w.w);
#pragma unroll
            for (int i = 0; i < 8; i++) {
                float xk = (kk == 0) ? xv[i].x : (kk == 1) ? xv[i].y
                         : (kk == 2) ? xv[i].z : xv[i].w;
                unsigned long long xx = pack2(xk, xk);
                a01[i] = ffma2(xx, w01, a01[i]);
                a23[i] = ffma2(xx, w23, a23[i]);
            }
        }
    }

#pragma unroll
    for (int i = 0; i < 8; i++) {
        long long row = rowbase + r0 + i;
        if (row < N_NODES) {
            float b0, b1, b2, b3;
            unpack2(a01[i], b0, b1);
            unpack2(a23[i], b2, b3);
            __half2* dst = &g_hh[row * 32 + (c0 >> 1)];
            dst[0] = __floats2half2_rn(b0, b1);
            dst[1] = __floats2half2_rn(b2, b3);
        }
    }
}

// ---------------------------------------------------------------------------
// K2: single-kernel scan -> offcnt (fused), cursors, dinv.
// ---------------------------------------------------------------------------
__global__ __launch_bounds__(256) void k_scan() {
    __shared__ int wsum[8], woff[8];
    __shared__ int sBase;
    int tid = threadIdx.x;
    int lane = tid & 31, wid = tid >> 5;

    int nPre = blockIdx.x * SCAN_CHUNK;
    int pre = 0;
#pragma unroll 4
    for (int i = tid * 4; i < nPre; i += 256 * 4) {
        int4 v = *(const int4*)&g_cnt[i];
        pre += v.x + v.y + v.z + v.w;
    }
#pragma unroll
    for (int o = 16; o; o >>= 1) pre += __shfl_down_sync(0xFFFFFFFFu, pre, o);
    if (lane == 0) wsum[wid] = pre;
    __syncthreads();
    if (tid == 0) {
        int t = 0;
#pragma unroll
        for (int i = 0; i < 8; i++) t += wsum[i];
        sBase = t;
    }
    __syncthreads();

    int base = blockIdx.x * SCAN_CHUNK + tid * 4;
    int v[4];
    if (base + 3 < N_NODES) {
        int4 t = *(const int4*)&g_cnt[base];
        v[0] = t.x; v[1] = t.y; v[2] = t.z; v[3] = t.w;
    } else {
#pragma unroll
        for (int j = 0; j < 4; j++)
            v[j] = (base + j < N_NODES) ? g_cnt[base + j] : 0;
    }
    int tsum = v[0] + v[1] + v[2] + v[3];

    int inc = tsum;
#pragma unroll
    for (int o = 1; o < 32; o <<= 1) {
        int y = __shfl_up_sync(0xFFFFFFFFu, inc, o);
        if (lane >= o) inc += y;
    }
    if (lane == 31) wsum[wid] = inc;
    __syncthreads();
    if (wid == 0) {
        int s = (lane < 8) ? wsum[lane] : 0;
        int orig = s;
#pragma unroll
        for (int o = 1; o < 8; o <<= 1) {
            int y = __shfl_up_sync(0xFFFFFFFFu, s, o);
            if (lane >= o) s += y;
        }
        if (lane < 8) woff[lane] = s - orig;
    }
    __syncthreads();

    int off = sBase + woff[wid] + (inc - tsum);
#pragma unroll
    for (int j = 0; j < 4; j++) {
        int i = base + j;
        if (i < N_NODES) {
            g_offcnt[i] = make_int2(off, v[j]);
            g_cursor[i] = off;
            g_dinv[i] = rsqrtf(1.0f + (float)v[j]);
        }
        off += v[j];
    }
}

// ---------------------------------------------------------------------------
// K3: hh pre-scale (blocks 0..SCALE_BLOCKS, FIRST so it overlaps fill)
//     + bucket fill (remaining blocks, 1 edge/thread).
// ---------------------------------------------------------------------------
__global__ __launch_bounds__(256) void k_fill(const int* __restrict__ ei) {
    if (blockIdx.x < SCALE_BLOCKS) {
        int w = threadIdx.x >> 5;
        int l = threadIdx.x & 31;
        int rowbase = blockIdx.x * SCALE_ROWS + w * 16;
#pragma unroll
        for (int i = 0; i < 16; i++) {
            int row = rowbase + i;
            if (row < N_NODES) {
                float d = g_dinv[row];
                unsigned idx = (unsigned)row * 32u + l;
                float2 v = __half22float2(g_hh[idx]);
                g_hh[idx] = __floats2half2_rn(v.x * d, v.y * d);
            }
        }
        return;
    }
    int e = (blockIdx.x - SCALE_BLOCKS) * 256 + threadIdx.x;
    if (e < N_EDGES) {
        int src = ei[e];
        int dst = ei[N_EDGES + e];
        g_srcs[atomicAdd(&g_cursor[dst], 1)] = src;
    }
}

// ---------------------------------------------------------------------------
// K4: gather + LN + ReLU + x-gate -> g_rs (fp16).
// 2 nodes per warp (16 lanes x 4 cols); fp16 pairwise batch accumulation.
// __launch_bounds__(256, 8) caps regs at 32 so the hadd2 diet and the R14
// occupancy (8 blocks/SM) compose instead of trading off.
// ---------------------------------------------------------------------------
__global__ __launch_bounds__(256, 8) void k_gather_ln(
        const float* __restrict__ x,
        const float* __restrict__ b,
        const float* __restrict__ gamma,
        const float* __restrict__ beta) {
    __shared__ float sb[64], sg[64], sbe[64];

    int tid = threadIdx.x;
    int rowbase = blockIdx.x * GL_ROWS;

    if (tid < 64) {
        sb[tid] = b[tid];
        sg[tid] = gamma[tid];
        sbe[tid] = beta[tid];
    }
    __syncthreads();

    int w = tid >> 5;          // warp 0..7
    int l = tid & 31;
    int h = l >> 4;            // which node of the pair (0/1)
    int c = l & 15;            // col group: cols 4c..4c+3
    int cc = 4 * c;

#pragma unroll
    for (int p = 0; p < 4; p++) {
        int node = rowbase + w * 8 + p * 2 + h;
        bool valid = node < N_NODES;

        int start = 0, deg = 0;
        float dinv = 0.f;
        float4 xv = make_float4(0.f, 0.f, 0.f, 0.f);
        if (valid) {
            int2 oc = g_offcnt[node];
            start = oc.x;
            deg = oc.y;
            dinv = g_dinv[node];
            xv = *(const float4*)&x[(unsigned)node * 64u + cc];  // prefetch gate
        }

        // self-loop term (hh already scaled by dinv[node])
        float a0 = 0.f, a1 = 0.f, a2 = 0.f, a3 = 0.f;
        if (valid) {
            uint2 u = *(const uint2*)&g_hh[(unsigned)node * 32u + 2 * c];
            float2 lo = __half22float2(*reinterpret_cast<__half2*>(&u.x));
            float2 hi = __half22float2(*reinterpret_cast<__half2*>(&u.y));
            a0 = lo.x; a1 = lo.y; a2 = hi.x; a3 = hi.y;
        }

        // warp-uniform trip count; per-slot predication
        int degMax = max(deg, __shfl_xor_sync(0xFFFFFFFFu, deg, 16));
        for (int it = 0; it < degMax; it += 4) {
            unsigned s[4];
            bool pq[4];
#pragma unroll
            for (int j = 0; j < 4; j++) {
                pq[j] = (it + j) < deg;
                s[j] = pq[j] ? (unsigned)g_srcs[start + it + j] : 0u;
            }
            uint2 u[4];
#pragma unroll
            for (int j = 0; j < 4; j++)
                u[j] = pq[j] ? *(const uint2*)&g_hh[s[j] * 32u + 2 * c]
                             : make_uint2(0u, 0u);
            // pairwise fp16 tree per column pair (same columns across nbrs)
            __half2 hx = __hadd2(__hadd2(*reinterpret_cast<__half2*>(&u[0].x),
                                         *reinterpret_cast<__half2*>(&u[1].x)),
                                 __hadd2(*reinterpret_cast<__half2*>(&u[2].x),
                                         *reinterpret_cast<__half2*>(&u[3].x)));
            __half2 hy = __hadd2(__hadd2(*reinterpret_cast<__half2*>(&u[0].y),
                                         *reinterpret_cast<__half2*>(&u[1].y)),
                                 __hadd2(*reinterpret_cast<__half2*>(&u[2].y),
                                         *reinterpret_cast<__half2*>(&u[3].y)));
            float2 fx = __half22float2(hx);
            float2 fy = __half22float2(hy);
            a0 += fx.x; a1 += fx.y; a2 += fy.x; a3 += fy.y;
        }

        float v0 = a0 * dinv + sb[cc];
        float v1 = a1 * dinv + sb[cc + 1];
        float v2 = a2 * dinv + sb[cc + 2];
        float v3 = a3 * dinv + sb[cc + 3];

        float s4 = v0 + v1 + v2 + v3;
        float q4 = v0 * v0 + v1 * v1 + v2 * v2 + v3 * v3;
#pragma unroll
        for (int o = 8; o; o >>= 1) {     // reduce over 16 lanes
            s4 += __shfl_xor_sync(0xFFFFFFFFu, s4, o);
            q4 += __shfl_xor_sync(0xFFFFFFFFu, q4, o);
        }
        float mu = s4 * (1.0f / 64.0f);
        float var = q4 * (1.0f / 64.0f) - mu * mu;
        float inv = rsqrtf(var + 1e-5f);

        if (valid) {
            float t0 = fmaxf((v0 - mu) * inv * sg[cc]     + sbe[cc],     0.f) * xv.x;
            float t1 = fmaxf((v1 - mu) * inv * sg[cc + 1] + sbe[cc + 1], 0.f) * xv.y;
            float t2 = fmaxf((v2 - mu) * inv * sg[cc + 2] + sbe[cc + 2], 0.f) * xv.z;
            float t3 = fmaxf((v3 - mu) * inv * sg[cc + 3] + sbe[cc + 3], 0.f) * xv.w;
            uint2 o2;
            __half2 h01 = __floats2half2_rn(t0, t1);
            __half2 h23 = __floats2half2_rn(t2, t3);
            o2.x = *reinterpret_cast<unsigned*>(&h01);
            o2.y = *reinterpret_cast<unsigned*>(&h23);
            *(uint2*)&g_rs[(unsigned)node * 32u + 2 * c] = o2;
        }
    }
}

// ---------------------------------------------------------------------------
// K5: GEMM2 — out = rs @ fcW + fcb. 128-row tiles, 8x4 micro-tile (same
// proven shape as K1's GEMM): halves Ws refetch + block count vs 64-row.
// fp16->fp32 conversion once at staging. Also resets g_cnt for next run.
// ---------------------------------------------------------------------------
__global__ __launch_bounds__(256) void k_gemm2(const float* __restrict__ fcW,
                                               const float* __restrict__ fcb,
                                               float* __restrict__ out) {
    __shared__ float Ws[64 * 64];
    __shared__ float xs[G2_ROWS][68];
    __shared__ float sfcb[64];

    int tid = threadIdx.x;
    int rowbase = blockIdx.x * G2_ROWS;

#pragma unroll
    for (int i = 0; i < 4; i++)
        ((float4*)Ws)[tid + 256 * i] = ((const float4*)fcW)[tid + 256 * i];
    if (tid < 64) sfcb[tid] = fcb[tid];

    // stage 128x64 rs tile, converting fp16 -> fp32: 8 uint2 per thread
#pragma unroll
    for (int i = 0; i < 8; i++) {
        int f = tid + i * 256;          // 0..2047
        int r = f >> 4, kq = f & 15;
        int row = rowbase + r;
        uint2 u = make_uint2(0u, 0u);
        if (row < N_NODES) u = *(const uint2*)&g_rs[(unsigned)row * 32u + kq * 2];
        float2 lo = __half22float2(*reinterpret_cast<__half2*>(&u.x));
        float2 hi = __half22float2(*reinterpret_cast<__half2*>(&u.y));
        *(float4*)&xs[r][kq * 4] = make_float4(lo.x, lo.y, hi.x, hi.y);
    }

    if (tid < G2_ROWS) {
        int row = rowbase + tid;
        if (row < N_NODES) g_cnt[row] = 0;
    }
    __syncthreads();

    int tx = tid & 15;
    int ty = tid >> 4;
    int r0 = ty * 8;
    int c0 = tx * 4;

    unsigned long long a01[8], a23[8];
#pragma unroll
    for (int i = 0; i < 8; i++) { a01[i] = 0ull; a23[i] = 0ull; }

#pragma unroll
    for (int k0 = 0; k0 < 64; k0 += 4) {
        float4 xv[8];
#pragma unroll
        for (int i = 0; i < 8; i++) xv[i] = *(float4*)&xs[r0 + i][k0];
#pragma unroll
        for (int kk = 0; kk < 4; kk++) {
            float4 wv = *(float4*)&Ws[(k0 + kk) * 64 + c0];
            unsigned long long w01 = pack2(wv.x, wv.y);
            unsigned long long w23 = pack2(wv.z, wv.w);
#pragma unroll
            for (int i = 0; i < 8; i++) {
                float xk = (kk == 0) ? xv[i].x : (kk == 1) ? xv[i].y
                         : (kk == 2) ? xv[i].z : xv[i].w;
                unsigned long long xx = pack2(xk, xk);
                a01[i] = ffma2(xx, w01, a01[i]);
                a23[i] = ffma2(xx, w23, a23[i]);
            }
        }
    }

#pragma unroll
    for (int i = 0; i < 8; i++) {
        int row = rowbase + r0 + i;
        if (row < N_NODES) {
            float b0, b1, b2, b3;
            unpack2(a01[i], b0, b1);
            unpack2(a23[i], b2, b3);
            *(float4*)&out[(unsigned)row * 64u + c0] =
                make_float4(b0 + sfcb[c0], b1 + sfcb[c0 + 1],
                            b2 + sfcb[c0 + 2], b3 + sfcb[c0 + 3]);
        }
    }
}

// ---------------------------------------------------------------------------
extern "C" void kernel_launch(void* const* d_in, const int* in_sizes, int n_in,
                              void* d_out, int out_size) {
    const float* x     = (const float*)d_in[0];
    const int*   ei    = (const int*)d_in[1];   // int32 per harness metadata
    const float* W     = (const float*)d_in[2];
    const float* b     = (const float*)d_in[3];
    const float* gamma = (const float*)d_in[4];
    const float* beta  = (const float*)d_in[5];
    const float* fcW   = (const float*)d_in[6];
    const float* fcb   = (const float*)d_in[7];
    float* out = (float*)d_out;

    (void)in_sizes; (void)n_in; (void)out_size;

    k_count_gemm<<<G1_TILES + COUNT_BLOCKS, 256>>>(x, W, ei);
    k_scan<<<NB_SCAN, 256>>>();
    k_fill<<<SCALE_BLOCKS + FILL_BLOCKS, 256>>>(ei);
    k_gather_ln<<<GL_TILES, 256>>>(x, b, gamma, beta);
    k_gemm2<<<G2_TILES, 256>>>(fcW, fcb, out);
}